// round 7
// baseline (speedup 1.0000x reference)
#include <cuda_runtime.h>
#include <cstdint>

// CRF forward scan — 2 BATCHES PER BLOCK (64 threads), thread j = state j for
// both batches. Two independent recurrence chains interleaved per thread (ILP).
// alpha' kept in base-2 scale: alpha' = alpha*log2(e), so exp/log are bare
// MUFU EX2/LG2. W[i][j] = exp(trans[i][j]-c_j); c'_j = c_j*log2(e).
// m' is a stale-by-2 block max per batch. Split matvec around the one barrier.
// feats+masks staged CHUNK steps ahead via cp.async 3-buffer pipeline.

#define TT 64
#define CHUNK 16
#define L2E 1.4426950408889634f
#define LN2 0.6931471805599453f
typedef unsigned long long u64;

__device__ float g_Wt[TT * TT];  // g_Wt[j*64+i] = exp(trans[i][j]-c_j)
__device__ float g_c2[TT];       // c_j * log2(e)

__device__ __forceinline__ u64 pack2(float lo, float hi) {
    u64 r; asm("mov.b64 %0, {%1, %2};" : "=l"(r) : "f"(lo), "f"(hi)); return r;
}
__device__ __forceinline__ void unpack2(u64 v, float& lo, float& hi) {
    asm("mov.b64 {%0, %1}, %2;" : "=f"(lo), "=f"(hi) : "l"(v));
}
__device__ __forceinline__ u64 ffma2(u64 a, u64 b, u64 c) {
    u64 d; asm("fma.rn.f32x2 %0, %1, %2, %3;" : "=l"(d) : "l"(a), "l"(b), "l"(c)); return d;
}
__device__ __forceinline__ u64 fadd2(u64 a, u64 b) {
    u64 d; asm("add.rn.f32x2 %0, %1, %2;" : "=l"(d) : "l"(a), "l"(b)); return d;
}
__device__ __forceinline__ uint32_t smem_u32(const void* p) {
    uint32_t a;
    asm("{ .reg .u64 t; cvta.to.shared.u64 t, %1; cvt.u32.u64 %0, t; }" : "=r"(a) : "l"(p));
    return a;
}

// ---------------------------------------------------------------------------
__global__ void crf_prep_kernel(const float* __restrict__ trans) {
    int j = threadIdx.x;
    float c = -3.402823466e+38f;
    #pragma unroll
    for (int i = 0; i < TT; i++) c = fmaxf(c, trans[i * TT + j]);
    g_c2[j] = c * L2E;
    #pragma unroll
    for (int i = 0; i < TT; i++) g_Wt[j * TT + i] = __expf(trans[i * TT + j] - c);
}

// ---------------------------------------------------------------------------
__global__ void __launch_bounds__(64) crf_scan_kernel(
    const float* __restrict__ feats,   // [B, S, 64]
    const float* __restrict__ masks,   // [B, S]
    float* __restrict__ out,           // [B, 64]
    int Sdim, int Bn)
{
    const int j    = threadIdx.x;
    const int warp = j >> 5;
    const int lane = j & 31;
    const int b0   = blockIdx.x * 2;
    const bool has2 = (b0 + 1 < Bn);
    const int b1   = has2 ? (b0 + 1) : b0;

    __shared__ float s_feat[2][3][CHUNK][TT];   // 24 KB
    __shared__ float s_mask[2][3][CHUNK];
    __shared__ float s_v[2][2][TT];             // [batch][buf][state]
    __shared__ float s_wm[2][4][2];             // per-batch stale-max ring

    // W column j split into own-warp half / other half (constant reg indices).
    u64 wlo[16], whi[16];
    {
        const float4* plo = reinterpret_cast<const float4*>(&g_Wt[j * TT + 32 * warp]);
        const float4* phi = reinterpret_cast<const float4*>(&g_Wt[j * TT + 32 * (warp ^ 1)]);
        #pragma unroll
        for (int q = 0; q < 8; q++) {
            float4 fl = plo[q];
            wlo[2 * q]     = pack2(fl.x, fl.y);
            wlo[2 * q + 1] = pack2(fl.z, fl.w);
            float4 fh = phi[q];
            whi[2 * q]     = pack2(fh.x, fh.y);
            whi[2 * q + 1] = pack2(fh.z, fh.w);
        }
    }
    const float cj2 = g_c2[j];

    const float* fb0 = feats + (size_t)b0 * Sdim * TT;
    const float* fb1 = feats + (size_t)b1 * Sdim * TT;
    const float* mb0 = masks + (size_t)b0 * Sdim;
    const float* mb1 = masks + (size_t)b1 * Sdim;
    const uint32_t feat_s0 = smem_u32(&s_feat[0][0][0][0]);
    const uint32_t feat_s1 = smem_u32(&s_feat[1][0][0][0]);
    const uint32_t mask_s  = smem_u32(&s_mask[0][0][0]);

    const int NC = (Sdim + CHUNK - 1) / CHUNK;

    // Stage chunk c for both batches — fully async.
    auto stage = [&](int c) {
        const int base = c * CHUNK;
        const int bufo = (c % 3) * CHUNK * TT;
        #pragma unroll
        for (int q = 0; q < 4; q++) {
            int g   = q * 64 + j;            // 16B granule 0..255
            int row = g >> 4;
            int col = (g & 15) << 2;
            int gr  = base + row; if (gr >= Sdim) gr = Sdim - 1;
            const float* s0 = fb0 + (size_t)gr * TT + col;
            const float* s1 = fb1 + (size_t)gr * TT + col;
            uint32_t off = (uint32_t)(bufo + row * TT + col) * 4u;
            asm volatile("cp.async.cg.shared.global [%0], [%1], 16;" :: "r"(feat_s0 + off), "l"(s0));
            asm volatile("cp.async.cg.shared.global [%0], [%1], 16;" :: "r"(feat_s1 + off), "l"(s1));
        }
        if (j < 2 * CHUNK) {                 // 32 mask words (both batches)
            int bt = j >> 4;                 // 0 or 1
            int rr = j & 15;
            int gr = base + rr; if (gr >= Sdim) gr = Sdim - 1;
            const float* src = (bt ? mb1 : mb0) + gr;
            uint32_t dst = mask_s + (uint32_t)((bt * 3 + (c % 3)) * CHUNK + rr) * 4u;
            asm volatile("cp.async.ca.shared.global [%0], [%1], 4;" :: "r"(dst), "l"(src));
        }
    };

    stage(0);
    asm volatile("cp.async.commit_group;");
    if (NC > 1) stage(1);
    asm volatile("cp.async.commit_group;");
    asm volatile("cp.async.wait_group 1;");
    __syncthreads();

    // alpha in base-2 scale.
    float aX = s_feat[0][0][0][j] * L2E;
    float aY = s_feat[1][0][0][j] * L2E;

    // Exact initial shifts; seed rings for step 1.
    {
        float wx = aX, wy = aY;
        #pragma unroll
        for (int o = 16; o > 0; o >>= 1) {
            wx = fmaxf(wx, __shfl_xor_sync(0xffffffffu, wx, o));
            wy = fmaxf(wy, __shfl_xor_sync(0xffffffffu, wy, o));
        }
        if (lane == 0) { s_wm[0][1][warp] = wx; s_wm[1][1][warp] = wy; }
    }
    __syncthreads();
    float mX = fmaxf(s_wm[0][1][0], s_wm[0][1][1]);
    float mY = fmaxf(s_wm[1][1][0], s_wm[1][1][1]);

    for (int c = 0; c < NC; c++) {
        if (c > 0) asm volatile("cp.async.wait_group 1;");
        if (c + 2 < NC) stage(c + 2);
        asm volatile("cp.async.commit_group;");
        __syncthreads();

        #pragma unroll 4
        for (int r = 0; r < CHUNK; r++) {
            const int t = c * CHUNK + r;
            if (t >= 1 && t < Sdim) {
                // exp2 with stale shift; publish v for both batches.
                const float vX = exp2f(aX - mX);
                const float vY = exp2f(aY - mY);
                s_v[0][r & 1][j] = vX;
                s_v[1][r & 1][j] = vY;
                __syncwarp();

                // Own-half matvec, both batches interleaved.
                const float4* vloX = reinterpret_cast<const float4*>(&s_v[0][r & 1][32 * warp]);
                const float4* vloY = reinterpret_cast<const float4*>(&s_v[1][r & 1][32 * warp]);
                u64 accX[4] = {0ull, 0ull, 0ull, 0ull};
                u64 accY[4] = {0ull, 0ull, 0ull, 0ull};
                #pragma unroll
                for (int q = 0; q < 8; q++) {
                    float4 fx = vloX[q];
                    accX[(2 * q) & 3]     = ffma2(pack2(fx.x, fx.y), wlo[2 * q],     accX[(2 * q) & 3]);
                    accX[(2 * q + 1) & 3] = ffma2(pack2(fx.z, fx.w), wlo[2 * q + 1], accX[(2 * q + 1) & 3]);
                    float4 fy = vloY[q];
                    accY[(2 * q) & 3]     = ffma2(pack2(fy.x, fy.y), wlo[2 * q],     accY[(2 * q) & 3]);
                    accY[(2 * q + 1) & 3] = ffma2(pack2(fy.z, fy.w), wlo[2 * q + 1], accY[(2 * q + 1) & 3]);
                }

                // Off-chain: feats (scaled), masks, stale-max trees.
                const float ftX = s_feat[0][c % 3][r][j] * L2E;
                const float ftY = s_feat[1][c % 3][r][j] * L2E;
                const float mkX = s_mask[0][c % 3][r];
                const float mkY = s_mask[1][c % 3][r];
                const float mnX = fmaxf(s_wm[0][r & 3][0], s_wm[0][r & 3][1]);
                const float mnY = fmaxf(s_wm[1][r & 3][0], s_wm[1][r & 3][1]);
                float wx = aX, wy = aY;
                #pragma unroll
                for (int o = 16; o > 0; o >>= 1) {
                    wx = fmaxf(wx, __shfl_xor_sync(0xffffffffu, wx, o));
                    wy = fmaxf(wy, __shfl_xor_sync(0xffffffffu, wy, o));
                }
                if (lane == 0) {
                    s_wm[0][(r + 1) & 3][warp] = wx;
                    s_wm[1][(r + 1) & 3][warp] = wy;
                }

                __syncthreads();   // other warp's v-halves visible

                // Other-half matvec, both batches.
                const float4* vhiX = reinterpret_cast<const float4*>(&s_v[0][r & 1][32 * (warp ^ 1)]);
                const float4* vhiY = reinterpret_cast<const float4*>(&s_v[1][r & 1][32 * (warp ^ 1)]);
                #pragma unroll
                for (int q = 0; q < 8; q++) {
                    float4 fx = vhiX[q];
                    accX[(2 * q) & 3]     = ffma2(pack2(fx.x, fx.y), whi[2 * q],     accX[(2 * q) & 3]);
                    accX[(2 * q + 1) & 3] = ffma2(pack2(fx.z, fx.w), whi[2 * q + 1], accX[(2 * q + 1) & 3]);
                    float4 fy = vhiY[q];
                    accY[(2 * q) & 3]     = ffma2(pack2(fy.x, fy.y), whi[2 * q],     accY[(2 * q) & 3]);
                    accY[(2 * q + 1) & 3] = ffma2(pack2(fy.z, fy.w), whi[2 * q + 1], accY[(2 * q + 1) & 3]);
                }
                u64 sX = fadd2(fadd2(accX[0], accX[1]), fadd2(accX[2], accX[3]));
                u64 sY = fadd2(fadd2(accY[0], accY[1]), fadd2(accY[2], accY[3]));
                float xl, xh, yl, yh;
                unpack2(sX, xl, xh);
                unpack2(sY, yl, yh);
                const float PX = xl + xh;
                const float PY = yl + yh;

                const float naX = ftX + cj2 + mX + log2f(PX);
                const float naY = ftY + cj2 + mY + log2f(PY);
                aX = naX * mkX + aX * (1.0f - mkX);
                aY = naY * mkY + aY * (1.0f - mkY);
                mX = mnX;
                mY = mnY;
            }
        }
    }

    out[(size_t)b0 * TT + j] = aX * LN2;
    if (has2) out[(size_t)b1 * TT + j] = aY * LN2;
}

// ---------------------------------------------------------------------------
extern "C" void kernel_launch(void* const* d_in, const int* in_sizes, int n_in,
                              void* d_out, int out_size) {
    const float* feats = (const float*)d_in[0];
    const float* masks = (const float*)d_in[1];
    const float* trans = (const float*)d_in[2];
    float* out = (float*)d_out;

    const int Bn   = out_size / TT;
    const int Sdim = in_sizes[0] / (Bn * TT);

    crf_prep_kernel<<<1, TT>>>(trans);
    crf_scan_kernel<<<(Bn + 1) / 2, TT>>>(feats, masks, out, Sdim, Bn);
}

// round 8
// speedup vs baseline: 1.6557x; 1.6557x over previous
#include <cuda_runtime.h>
#include <cstdint>

// CRF forward scan, 512 blocks x 64 threads. Thread tid=32w+l owns state tid.
// Per step, thread (w,l) computes PARTIAL sums over its own warp's v-half
// (rows [32w,32w+32)) for BOTH columns l and l+32; keeps the partial for its
// owned state, publishes the other (1 float). Cross-warp traffic = 1 float.
// alpha kept base-2 scaled; ex2/lg2 via raw PTX approx ops.
// m = stale-by-2 block max (LSE shift-invariant). feats/masks via cp.async.

#define TT 64
#define CHUNK 16
#define L2E 1.4426950408889634f
#define LN2 0.6931471805599453f
typedef unsigned long long u64;

__device__ float g_Wt[TT * TT];  // g_Wt[j*64+i] = exp(trans[i][j]-c_j)
__device__ float g_c2[TT];       // c_j * log2(e)

__device__ __forceinline__ u64 pack2(float lo, float hi) {
    u64 r; asm("mov.b64 %0, {%1, %2};" : "=l"(r) : "f"(lo), "f"(hi)); return r;
}
__device__ __forceinline__ void unpack2(u64 v, float& lo, float& hi) {
    asm("mov.b64 {%0, %1}, %2;" : "=f"(lo), "=f"(hi) : "l"(v));
}
__device__ __forceinline__ u64 ffma2(u64 a, u64 b, u64 c) {
    u64 d; asm("fma.rn.f32x2 %0, %1, %2, %3;" : "=l"(d) : "l"(a), "l"(b), "l"(c)); return d;
}
__device__ __forceinline__ u64 fadd2(u64 a, u64 b) {
    u64 d; asm("add.rn.f32x2 %0, %1, %2;" : "=l"(d) : "l"(a), "l"(b)); return d;
}
__device__ __forceinline__ float ex2f(float x) {
    float y; asm("ex2.approx.f32 %0, %1;" : "=f"(y) : "f"(x)); return y;
}
__device__ __forceinline__ float lg2f(float x) {
    float y; asm("lg2.approx.f32 %0, %1;" : "=f"(y) : "f"(x)); return y;
}
__device__ __forceinline__ uint32_t smem_u32(const void* p) {
    uint32_t a;
    asm("{ .reg .u64 t; cvta.to.shared.u64 t, %1; cvt.u32.u64 %0, t; }" : "=r"(a) : "l"(p));
    return a;
}
// Monotone float->int map for REDUX-based warp max.
__device__ __forceinline__ int fkey(float x) {
    int b = __float_as_int(x);
    return b >= 0 ? b : (b ^ 0x7fffffff);
}
__device__ __forceinline__ float funkey(int k) {
    return __int_as_float(k >= 0 ? k : (k ^ 0x7fffffff));
}

// ---------------------------------------------------------------------------
__global__ void crf_prep_kernel(const float* __restrict__ trans) {
    int j = threadIdx.x;
    float c = -3.402823466e+38f;
    #pragma unroll
    for (int i = 0; i < TT; i++) c = fmaxf(c, trans[i * TT + j]);
    g_c2[j] = c * L2E;
    #pragma unroll
    for (int i = 0; i < TT; i++) g_Wt[j * TT + i] = __expf(trans[i * TT + j] - c);
}

// ---------------------------------------------------------------------------
__global__ void __launch_bounds__(64) crf_scan_kernel(
    const float* __restrict__ feats,   // [B, S, 64]
    const float* __restrict__ masks,   // [B, S]
    float* __restrict__ out,           // [B, 64]
    int Sdim)
{
    const int b    = blockIdx.x;
    const int tid  = threadIdx.x;
    const int warp = tid >> 5;
    const int lane = tid & 31;

    __shared__ float s_feat[3][CHUNK][TT];   // 12 KB staged feats
    __shared__ float s_mask[3][CHUNK];
    __shared__ float s_v[TT];                // warp-private halves (no cross-read)
    __shared__ float s_part[2][TT];          // cross-warp partials, double buffered
    __shared__ float s_wm[4][2];             // stale-max ring

    // W for columns (lane, lane+32), OWN rows [32*warp, 32*warp+32),
    // packed in pairs along i (contiguous in g_Wt's row-j layout).
    u64 wA[16], wB[16];
    {
        const float4* pa = reinterpret_cast<const float4*>(&g_Wt[lane * TT + 32 * warp]);
        const float4* pb = reinterpret_cast<const float4*>(&g_Wt[(lane + 32) * TT + 32 * warp]);
        #pragma unroll
        for (int q = 0; q < 8; q++) {
            float4 fa = pa[q];
            wA[2 * q]     = pack2(fa.x, fa.y);
            wA[2 * q + 1] = pack2(fa.z, fa.w);
            float4 fb = pb[q];
            wB[2 * q]     = pack2(fb.x, fb.y);
            wB[2 * q + 1] = pack2(fb.z, fb.w);
        }
    }
    const float cj2 = g_c2[tid];

    const float* fbp = feats + (size_t)b * Sdim * TT;
    const float* mbp = masks + (size_t)b * Sdim;
    const uint32_t feat_s0 = smem_u32(&s_feat[0][0][0]);
    const uint32_t mask_s0 = smem_u32(&s_mask[0][0]);

    const int NC = (Sdim + CHUNK - 1) / CHUNK;

    auto stage = [&](int c) {
        const int base = c * CHUNK;
        const int bufo = (c % 3) * CHUNK * TT;
        #pragma unroll
        for (int q = 0; q < 4; q++) {
            int g   = q * 64 + tid;        // 16B granule 0..255
            int row = g >> 4;
            int col = (g & 15) << 2;
            int gr  = base + row; if (gr >= Sdim) gr = Sdim - 1;
            const float* src = fbp + (size_t)gr * TT + col;
            uint32_t dst = feat_s0 + (uint32_t)(bufo + row * TT + col) * 4u;
            asm volatile("cp.async.cg.shared.global [%0], [%1], 16;" :: "r"(dst), "l"(src));
        }
        if (tid < CHUNK) {
            int gr = base + tid; if (gr >= Sdim) gr = Sdim - 1;
            const float* src = mbp + gr;
            uint32_t dst = mask_s0 + (uint32_t)((c % 3) * CHUNK + tid) * 4u;
            asm volatile("cp.async.ca.shared.global [%0], [%1], 4;" :: "r"(dst), "l"(src));
        }
    };

    stage(0);
    asm volatile("cp.async.commit_group;");
    if (NC > 1) stage(1);
    asm volatile("cp.async.commit_group;");
    asm volatile("cp.async.wait_group 1;");
    __syncthreads();

    float alpha = s_feat[0][0][tid] * L2E;   // base-2 scaled alpha0

    // Exact initial shift; seed ring slot 1 (read at t=1 and t=2).
    {
        float wmx = funkey(__reduce_max_sync(0xffffffffu, fkey(alpha)));
        if (lane == 0) s_wm[1][warp] = wmx;
    }
    __syncthreads();
    float m = fmaxf(s_wm[1][0], s_wm[1][1]);

    for (int c = 0; c < NC; c++) {
        if (c > 0) asm volatile("cp.async.wait_group 1;");
        if (c + 2 < NC) stage(c + 2);
        asm volatile("cp.async.commit_group;");
        __syncthreads();

        #pragma unroll
        for (int r = 0; r < CHUNK; r++) {
            const int t = c * CHUNK + r;
            if (t >= 1 && t < Sdim) {
                // Chain head: exp2 with stale shift, publish own v.
                const float v = ex2f(alpha - m);
                s_v[tid] = v;

                // Off-chain: staged feat/mask, blend precompute, stale max.
                const float ft  = s_feat[c % 3][r][tid] * L2E;
                const float mk  = s_mask[c % 3][r];
                const float pre = ft + cj2 + m;
                const float t0  = pre * mk + alpha * (1.0f - mk);
                const float mnext = fmaxf(s_wm[r & 3][0], s_wm[r & 3][1]);
                {
                    float wmx = funkey(__reduce_max_sync(0xffffffffu, fkey(alpha)));
                    if (lane == 0) s_wm[(r + 1) & 3][warp] = wmx;
                }

                __syncwarp();

                // Own-half matvec for columns lane and lane+32.
                const float4* vp = reinterpret_cast<const float4*>(&s_v[32 * warp]);
                u64 accA[4] = {0ull, 0ull, 0ull, 0ull};
                u64 accB[4] = {0ull, 0ull, 0ull, 0ull};
                #pragma unroll
                for (int q = 0; q < 8; q++) {
                    float4 f = vp[q];
                    u64 v01 = pack2(f.x, f.y);
                    u64 v23 = pack2(f.z, f.w);
                    accA[(2 * q) & 3]     = ffma2(v01, wA[2 * q],     accA[(2 * q) & 3]);
                    accA[(2 * q + 1) & 3] = ffma2(v23, wA[2 * q + 1], accA[(2 * q + 1) & 3]);
                    accB[(2 * q) & 3]     = ffma2(v01, wB[2 * q],     accB[(2 * q) & 3]);
                    accB[(2 * q + 1) & 3] = ffma2(v23, wB[2 * q + 1], accB[(2 * q + 1) & 3]);
                }
                u64 sA = fadd2(fadd2(accA[0], accA[1]), fadd2(accA[2], accA[3]));
                u64 sB = fadd2(fadd2(accB[0], accB[1]), fadd2(accB[2], accB[3]));
                float al, ah, bl, bh;
                unpack2(sA, al, ah);
                unpack2(sB, bl, bh);
                const float PA = al + ah;               // partial, column lane
                const float PB = bl + bh;               // partial, column lane+32

                // Keep the partial for the owned state; publish the other.
                const float keep = (warp == 0) ? PA : PB;
                const float pub  = (warp == 0) ? PB : PA;
                s_part[r & 1][tid ^ 32] = pub;

                __syncthreads();

                // Tail: combine halves, log2, blend.
                const float P = keep + s_part[r & 1][tid];
                alpha = fmaf(lg2f(P), mk, t0);
                m = mnext;
            }
        }
    }

    out[(size_t)b * TT + tid] = alpha * LN2;
}

// ---------------------------------------------------------------------------
extern "C" void kernel_launch(void* const* d_in, const int* in_sizes, int n_in,
                              void* d_out, int out_size) {
    const float* feats = (const float*)d_in[0];
    const float* masks = (const float*)d_in[1];
    const float* trans = (const float*)d_in[2];
    float* out = (float*)d_out;

    const int Bn   = out_size / TT;
    const int Sdim = in_sizes[0] / (Bn * TT);

    crf_prep_kernel<<<1, TT>>>(trans);
    crf_scan_kernel<<<Bn, TT>>>(feats, masks, out, Sdim);
}